// round 16
// baseline (speedup 1.0000x reference)
#include <cuda_runtime.h>
#include <cuda_fp16.h>
#include <math.h>
#include <cstdint>

#define Tn 1024
#define Bn 4
#define En 1024
#define Hn 16
#define DHn 64
#define RSPAN (2*Tn - 1)   // 2047
#define LOG2E 1.4426950408889634f

// ---------------- scratch ----------------
__device__ float g_gate[Bn*Hn*Tn];
__device__ float g_posb[Hn*RSPAN];

__device__ __half g_x[(size_t)Tn*Bn*En];       // activations (query, later ctx)
__device__ __half g_w[4][(size_t)En*En];       // weights

__device__ __half g_q1[(size_t)Bn*Hn*Tn*DHn];  // [B,H,T,DH]
__device__ __half g_k1[(size_t)Bn*Hn*Tn*DHn];
__device__ __half g_v1[(size_t)Bn*Hn*Tn*DHn];

// ================= helpers =================
__device__ __forceinline__ uint32_t smem_u32(const void* p) {
    uint32_t a;
    asm("{ .reg .u64 t; cvta.to.shared.u64 t, %1; cvt.u32.u64 %0, t; }" : "=r"(a) : "l"(p));
    return a;
}
__device__ __forceinline__ void cpa16(uint32_t dst, const void* src) {
    asm volatile("cp.async.cg.shared.global [%0], [%1], 16;" :: "r"(dst), "l"(src));
}
#define CP_COMMIT() asm volatile("cp.async.commit_group;" ::: "memory")
#define CP_WAIT(n)  asm volatile("cp.async.wait_group %0;" :: "n"(n) : "memory")

#define LDSM_X4(r, a) \
    asm volatile("ldmatrix.sync.aligned.m8n8.x4.shared.b16 {%0,%1,%2,%3}, [%4];" \
        : "=r"((r)[0]), "=r"((r)[1]), "=r"((r)[2]), "=r"((r)[3]) : "r"(a))
#define LDSM_X4_T(r, a) \
    asm volatile("ldmatrix.sync.aligned.m8n8.x4.trans.shared.b16 {%0,%1,%2,%3}, [%4];" \
        : "=r"((r)[0]), "=r"((r)[1]), "=r"((r)[2]), "=r"((r)[3]) : "r"(a))

#define MMAH(c, a, b0, b1) \
    asm volatile("mma.sync.aligned.m16n8k16.row.col.f32.f16.f16.f32 " \
        "{%0,%1,%2,%3}, {%4,%5,%6,%7}, {%8,%9}, {%0,%1,%2,%3};" \
        : "+f"((c)[0]), "+f"((c)[1]), "+f"((c)[2]), "+f"((c)[3]) \
        : "r"((a)[0]), "r"((a)[1]), "r"((a)[2]), "r"((a)[3]), "r"(b0), "r"(b1))

__device__ __forceinline__ uint32_t pack_h2(float lo, float hi) {
    uint32_t r;
    asm("cvt.rn.f16x2.f32 %0, %1, %2;" : "=r"(r) : "f"(hi), "f"(lo));
    return r;
}

// ================= fp16 GEMM (BK=64, 3-stage, 2 CTAs/SM) =================
#define TILE_B 16384             // 128 rows x 128 B
#define STAGE_B (2*TILE_B)       // A + W = 32768
#define NSTG 3
#define SMEM_G (NSTG*STAGE_B)    // 98304
#define NCH 16                   // K chunks of 64

__device__ __forceinline__ void load_tile_mma(uint32_t sdst, const __half* g,
                                              int r0, int kc, int tid) {
    #pragma unroll
    for (int it = 0; it < 4; it++) {
        int idx = tid + it * 256;
        int row = idx >> 3, seg = idx & 7;
        uint32_t dst = sdst + (uint32_t)row * 128u + (uint32_t)((seg ^ (row & 7)) << 4);
        const char* src = (const char*)(g + (size_t)(r0 + row) * 1024 + kc * 64 + seg * 8);
        cpa16(dst, src);
    }
}
__device__ __forceinline__ void load_stage(uint32_t bb,
        const __half* A, const __half* W, int m0, int n0, int kc, int tid) {
    load_tile_mma(bb, A, m0, kc, tid);
    load_tile_mma(bb + TILE_B, W, n0, kc, tid);
    CP_COMMIT();
}

__device__ __forceinline__ void gemm_mainloop(uint32_t sb,
        const __half* A, const __half* W,
        int m0, int n0, int tid, int wid, int lane, float acc[4][4][4]) {
    int warp_m = wid & 1;
    int warp_n = wid >> 1;
    const int lswz = lane & 7;
    const int ahib = lane >> 4;
    const int bhib = (lane >> 3) & 1;
    uint32_t a_base[4];
    #pragma unroll
    for (int mi = 0; mi < 4; mi++) {
        int arow = warp_m * 64 + mi * 16 + (lane & 15);
        a_base[mi] = (uint32_t)arow * 128u;
    }
    uint32_t b_base[2];
    #pragma unroll
    for (int nip = 0; nip < 2; nip++) {
        int nrow = warp_n * 32 + nip * 16 + ((lane >> 4) & 1) * 8 + (lane & 7);
        b_base[nip] = (uint32_t)nrow * 128u;
    }

    load_stage(sb + 0 * STAGE_B, A, W, m0, n0, 0, tid);
    load_stage(sb + 1 * STAGE_B, A, W, m0, n0, 1, tid);

    #pragma unroll 1
    for (int kc = 0; kc < NCH; kc++) {
        if (kc < NCH - 1) CP_WAIT(1); else CP_WAIT(0);
        __syncthreads();
        if (kc + 2 < NCH)
            load_stage(sb + ((kc + 2) % NSTG) * STAGE_B, A, W, m0, n0, kc + 2, tid);
        uint32_t bb = sb + (kc % NSTG) * STAGE_B;
        uint32_t At = bb, Wt = bb + TILE_B;
        #pragma unroll
        for (int ks = 0; ks < 4; ks++) {
            uint32_t asg = (uint32_t)(((ks * 2 + ahib) ^ lswz) << 4);
            uint32_t bsg = (uint32_t)(((ks * 2 + bhib) ^ lswz) << 4);
            uint32_t af[4][4], bf[2][4];
            #pragma unroll
            for (int nip = 0; nip < 2; nip++)
                LDSM_X4(bf[nip], Wt + b_base[nip] + bsg);
            #pragma unroll
            for (int mi = 0; mi < 4; mi++)
                LDSM_X4(af[mi], At + a_base[mi] + asg);
            #pragma unroll
            for (int mi = 0; mi < 4; mi++) {
                #pragma unroll
                for (int ni = 0; ni < 4; ni++) {
                    int nip = ni >> 1, hf = (ni & 1) * 2;
                    MMAH(acc[mi][ni], af[mi], bf[nip][hf], bf[nip][hf + 1]);
                }
            }
        }
    }
}

// fused QKV: grid (24, 32)
__global__ void __launch_bounds__(256, 2)
gemm_qkv(const __half* __restrict__ A,
         const float* __restrict__ q_b, const float* __restrict__ k_b,
         const float* __restrict__ v_b) {
    extern __shared__ char smraw[];
    uint32_t sb = smem_u32(smraw);
    int tid = threadIdx.x, wid = tid >> 5, lane = tid & 31;
    int w = blockIdx.x >> 3;
    int n0 = (blockIdx.x & 7) * 128, m0 = blockIdx.y * 128;

    const size_t NW = (size_t)En * En;
    const __half* W = &g_w[0][0] + (size_t)w * NW;
    const float* bias = (w == 0) ? q_b : (w == 1) ? k_b : v_b;
    __half* dst = (w == 0) ? g_q1 : (w == 1) ? g_k1 : g_v1;
    float scale = (w == 0) ? 0.125f * LOG2E : 1.0f;

    float acc[4][4][4];
    #pragma unroll
    for (int i = 0; i < 4; i++)
        #pragma unroll
        for (int j = 0; j < 4; j++)
            #pragma unroll
            for (int q = 0; q < 4; q++) acc[i][j][q] = 0.f;

    gemm_mainloop(sb, A, W, m0, n0, tid, wid, lane, acc);

    int rbase = m0 + (wid & 1) * 64 + (lane >> 2);
    int cbase = n0 + (wid >> 1) * 32 + (lane & 3) * 2;
    #pragma unroll
    for (int mi = 0; mi < 4; mi++) {
        #pragma unroll
        for (int ni = 0; ni < 4; ni++) {
            int c = cbase + ni * 8;
            float b0 = bias[c], b1 = bias[c + 1];
            #pragma unroll
            for (int half = 0; half < 2; half++) {
                int r = rbase + mi * 16 + half * 8;
                float v0 = (acc[mi][ni][half * 2 + 0] + b0) * scale;
                float v1 = (acc[mi][ni][half * 2 + 1] + b1) * scale;
                int t = r >> 2, b = r & 3;
                int h = c >> 6, d = c & 63;
                size_t ad = ((size_t)(b * Hn + h) * Tn + t) * DHn + d;
                *(uint32_t*)(dst + ad) = pack_h2(v0, v1);
            }
        }
    }
}

// out projection: fp32 output
__global__ void __launch_bounds__(256, 2)
gemm_out(const __half* __restrict__ A, const __half* __restrict__ W,
         const float* __restrict__ bias, float* __restrict__ outf) {
    extern __shared__ char smraw[];
    uint32_t sb = smem_u32(smraw);
    int tid = threadIdx.x, wid = tid >> 5, lane = tid & 31;
    int n0 = blockIdx.x * 128, m0 = blockIdx.y * 128;

    float acc[4][4][4];
    #pragma unroll
    for (int i = 0; i < 4; i++)
        #pragma unroll
        for (int j = 0; j < 4; j++)
            #pragma unroll
            for (int q = 0; q < 4; q++) acc[i][j][q] = 0.f;

    gemm_mainloop(sb, A, W, m0, n0, tid, wid, lane, acc);

    int rbase = m0 + (wid & 1) * 64 + (lane >> 2);
    int cbase = n0 + (wid >> 1) * 32 + (lane & 3) * 2;
    #pragma unroll
    for (int mi = 0; mi < 4; mi++) {
        #pragma unroll
        for (int ni = 0; ni < 4; ni++) {
            int c = cbase + ni * 8;
            float b0 = bias[c], b1 = bias[c + 1];
            #pragma unroll
            for (int half = 0; half < 2; half++) {
                int r = rbase + mi * 16 + half * 8;
                float2 v;
                v.x = acc[mi][ni][half * 2 + 0] + b0;
                v.y = acc[mi][ni][half * 2 + 1] + b1;
                *(float2*)(outf + (size_t)r * 1024 + c) = v;
            }
        }
    }
}

// ================= fused prep (16 floats/thread on bulk sections) =================
// [0,1024): query; [1024,2048): weights; [2048,2056): posb; [2056,10248): gate
#define PREP_BLOCKS 10248

__global__ void prep_kernel(const float* __restrict__ query,
                            const float* __restrict__ q_w, const float* __restrict__ k_w,
                            const float* __restrict__ v_w, const float* __restrict__ out_w,
                            const float* __restrict__ rel_bias,
                            const float* __restrict__ grep_w,
                            const float* __restrict__ grep_b,
                            const float* __restrict__ grep_a) {
    int bx = blockIdx.x, tid = threadIdx.x;
    if (bx < 1024) {
        size_t i = ((size_t)bx * 256 + tid) * 16;
        float4 v0 = *(const float4*)(query + i);
        float4 v1 = *(const float4*)(query + i + 4);
        float4 v2 = *(const float4*)(query + i + 8);
        float4 v3 = *(const float4*)(query + i + 12);
        uint32_t* xp = (uint32_t*)(g_x + i);
        xp[0] = pack_h2(v0.x, v0.y); xp[1] = pack_h2(v0.z, v0.w);
        xp[2] = pack_h2(v1.x, v1.y); xp[3] = pack_h2(v1.z, v1.w);
        xp[4] = pack_h2(v2.x, v2.y); xp[5] = pack_h2(v2.z, v2.w);
        xp[6] = pack_h2(v3.x, v3.y); xp[7] = pack_h2(v3.z, v3.w);
    } else if (bx < 2048) {
        const int NW = En * En;
        size_t i = ((size_t)(bx - 1024) * 256 + tid) * 16;
        int w = (int)(i / NW);
        size_t off = i - (size_t)w * NW;
        const float* src = (w == 0) ? q_w : (w == 1) ? k_w : (w == 2) ? v_w : out_w;
        float4 v0 = *(const float4*)(src + off);
        float4 v1 = *(const float4*)(src + off + 4);
        float4 v2 = *(const float4*)(src + off + 8);
        float4 v3 = *(const float4*)(src + off + 12);
        uint32_t* wp = (uint32_t*)(&g_w[0][0] + i);
        wp[0] = pack_h2(v0.x, v0.y); wp[1] = pack_h2(v0.z, v0.w);
        wp[2] = pack_h2(v1.x, v1.y); wp[3] = pack_h2(v1.z, v1.w);
        wp[4] = pack_h2(v2.x, v2.y); wp[5] = pack_h2(v2.z, v2.w);
        wp[6] = pack_h2(v3.x, v3.y); wp[7] = pack_h2(v3.z, v3.w);
    } else if (bx < 2056) {
        int idx = (bx - 2048) * 256 + tid;
        if (idx >= RSPAN) return;
        int rp = idx - (Tn - 1);
        const int n = 16, max_exact = 8;
        int bucket = (rp > 0) ? n : 0;
        int arp = abs(rp);
        int add;
        if (arp < max_exact) add = arp;
        else {
            float v = (log2f((float)arp) - 3.0f) * 2.0f;
            add = max_exact + (int)v;
            if (add > n - 1) add = n - 1;
        }
        bucket += add;
        #pragma unroll
        for (int h = 0; h < Hn; h++)
            g_posb[h*RSPAN + idx] = rel_bias[bucket*Hn + h];
    } else {
        int warp = (bx - 2056) * 8 + (tid >> 5);   // 8192 blocks -> 65536 warps
        int lane = tid & 31;
        int t = warp % Tn;
        int h = (warp / Tn) % Hn;
        int b = warp / (Tn * Hn);
        const float* q = query + ((size_t)t*Bn + b)*En + h*DHn;
        float q0 = q[lane], q1 = q[lane + 32];
        float s0 = 0.f, s1 = 0.f;
        #pragma unroll
        for (int e = 0; e < 8; e++) {
            float p = q0 * grep_w[e*DHn + lane] + q1 * grep_w[e*DHn + lane + 32];
            #pragma unroll
            for (int o = 16; o; o >>= 1) p += __shfl_xor_sync(0xffffffffu, p, o);
            p += grep_b[e];
            if (e < 4) s0 += p; else s1 += p;
        }
        if (lane == 0) {
            float ga = 1.f / (1.f + __expf(-s0));
            float gb = 1.f / (1.f + __expf(-s1));
            g_gate[warp] = (ga * (gb * grep_a[h] - 1.0f) + 2.0f) * LOG2E;
        }
    }
}

// ================= fp16 flash attention (128 q-rows, 8 warps, 5-stage, 2 CTAs/SM) =================
#define AT3   8192                  // 64 rows x 128 B per KV tile
#define ASTG2 (2*AT3)               // K + V = 16384 per stage
#define ANST  5
#define ASM_Q  (ANST*ASTG2)         // 81920 : Q (128 rows x 128 B = 16384)
#define ASM_LS (ASM_Q + 16384)      // 98304 : Ls[5][192] floats
#define ASM_GS (ASM_LS + ANST*192*4)// 102144 : gs 128 floats
#define ASM_TOTAL (ASM_GS + 768)    // 102912
#define NTILE 16

__device__ __forceinline__ void attn_load_kv(uint32_t bbase,
        const __half* kk, const __half* vv, int s0, int tid) {
    #pragma unroll
    for (int it = 0; it < 2; it++) {
        int idx = tid + it * 256;
        int row = idx >> 3, seg = idx & 7;
        uint32_t doff = (uint32_t)row * 128u + (uint32_t)((seg ^ (row & 7)) << 4);
        size_t goff = (size_t)(s0 + row) * 64 + seg * 8;
        cpa16(bbase + doff, kk + goff);
        cpa16(bbase + AT3 + doff, vv + goff);
    }
    CP_COMMIT();
}

__global__ void __launch_bounds__(256, 2) attn_mma() {
    extern __shared__ char smraw[];
    uint32_t sb = smem_u32(smraw);
    float* Lsf = (float*)(smraw + ASM_LS);
    float* gsf = (float*)(smraw + ASM_GS);
    const int tid = threadIdx.x, wid = tid >> 5, lane = tid & 31;
    const int t0 = blockIdx.x * 128;
    const int h = blockIdx.y, b = blockIdx.z;
    const size_t hoff = (size_t)(b*Hn + h) * Tn * DHn;
    const __half *qg = g_q1 + hoff;
    const __half *kkg = g_k1 + hoff, *vvg = g_v1 + hoff;
    const int lswz = lane & 7;

    // ---- prologue: Q group first, then KV stages 0..3 ----
    #pragma unroll
    for (int it = 0; it < 4; it++) {
        int idx = tid + it * 256;
        int row = idx >> 3, seg = idx & 7;
        uint32_t doff = (uint32_t)row * 128u + (uint32_t)((seg ^ (row & 7)) << 4);
        size_t goff = (size_t)(t0 + row) * 64 + seg * 8;
        cpa16(sb + ASM_Q + doff, qg + goff);
    }
    CP_COMMIT();
    #pragma unroll
    for (int ps = 0; ps < 4; ps++)
        attn_load_kv(sb + ps * ASTG2, kkg, vvg, ps * 64, tid);
    if (tid < 128) gsf[tid] = g_gate[(b*Hn + h)*Tn + t0 + tid];
    if (tid < 191) {
        #pragma unroll
        for (int ps = 0; ps < 4; ps++)
            Lsf[ps*192 + tid] = g_posb[h*RSPAN + 1023 + (ps*64 - t0) + tid - 127];
    }
    CP_WAIT(4); __syncthreads();    // Q complete (4 younger KV groups pending)

    uint32_t qf[4][4];
    {
        int arow = wid * 16 + (lane & 15);
        #pragma unroll
        for (int kt = 0; kt < 4; kt++) {
            int seg = kt * 2 + (lane >> 4);
            uint32_t aoff = (uint32_t)arow * 128u + (uint32_t)((seg ^ (arow & 7)) << 4);
            LDSM_X4(qf[kt], sb + ASM_Q + aoff);
        }
    }

    float O[8][4];
    #pragma unroll
    for (int j = 0; j < 8; j++) { O[j][0]=0.f; O[j][1]=0.f; O[j][2]=0.f; O[j][3]=0.f; }
    float m0r = -1e30f, m1r = -1e30f, l0r = 0.f, l1r = 0.f;

    const int r0l = wid * 16 + (lane >> 2);   // 0..127
    const int cb  = (lane & 3) * 2;
    const float g0 = gsf[r0l], g1 = gsf[r0l + 8];
    const int ib0 = 127 - r0l + cb;
    const int ib1 = ib0 - 8;

    #pragma unroll 1
    for (int st = 0; st < NTILE; st++) {
        CP_WAIT(3);
        __syncthreads();
        if (st + 4 < NTILE) {
            int ns = (st + 4) % ANST;
            attn_load_kv(sb + ns * ASTG2, kkg, vvg, (st + 4) * 64, tid);
            if (tid < 191)
                Lsf[ns * 192 + tid] =
                    g_posb[h*RSPAN + 1023 + ((st + 4) * 64 - t0) + tid - 127];
        } else {
            CP_COMMIT();
        }
        uint32_t bb = sb + (st % ANST) * ASTG2;
        float* Lss = Lsf + (st % ANST) * 192;

        // ---- S init = gate*posb; S += Q K^T ----
        float S[8][4];
        #pragma unroll
        for (int j = 0; j < 8; j++) {
            S[j][0] = g0 * Lss[ib0 + 8*j];
            S[j][1] = g0 * Lss[ib0 + 8*j + 1];
            S[j][2] = g1 * Lss[ib1 + 8*j];
            S[j][3] = g1 * Lss[ib1 + 8*j + 1];
        }
        #pragma unroll
        for (int kt = 0; kt < 4; kt++) {
            #pragma unroll
            for (int nip = 0; nip < 4; nip++) {
                int krow = nip*16 + ((lane >> 4) & 1)*8 + (lane & 7);
                int kseg = kt*2 + ((lane >> 3) & 1);
                uint32_t boff = (uint32_t)krow * 128u + (uint32_t)((kseg ^ lswz) << 4);
                uint32_t bf[4];
                LDSM_X4(bf, bb + boff);
                MMAH(S[nip*2 + 0], qf[kt], bf[0], bf[1]);
                MMAH(S[nip*2 + 1], qf[kt], bf[2], bf[3]);
            }
        }

        // ---- online softmax (base-2) ----
        {
            float tm = fmaxf(S[0][0], S[0][1]);
            #pragma unroll
            for (int j = 1; j < 8; j++) tm = fmaxf(tm, fmaxf(S[j][0], S[j][1]));
            tm = fmaxf(tm, __shfl_xor_sync(0xffffffffu, tm, 1));
            tm = fmaxf(tm, __shfl_xor_sync(0xffffffffu, tm, 2));
            float mn = fmaxf(m0r, tm);
            float corr = exp2f(m0r - mn);
            m0r = mn;
            float rs = 0.f;
            #pragma unroll
            for (int j = 0; j < 8; j++) {
                S[j][0] = exp2f(S[j][0] - mn);
                S[j][1] = exp2f(S[j][1] - mn);
                rs += S[j][0] + S[j][1];
            }
            rs += __shfl_xor_sync(0xffffffffu, rs, 1);
            rs += __shfl_xor_sync(0xffffffffu, rs, 2);
            l0r = l0r * corr + rs;
            #pragma unroll
            for (int j = 0; j < 8; j++) { O[j][0] *= corr; O[j][1] *= corr; }
        }
        {
            float tm = fmaxf(S[0][2], S[0][3]);
            #pragma unroll
            for (int j = 1; j < 8; j++) tm = fmaxf(tm, fmaxf(S[j][2], S[j][3]));
            tm = fmaxf(tm, __shfl_xor_sync(0xffffffffu, tm, 1));
            tm = fmaxf(tm, __shfl_xor_sync(0xffffffffu, tm, 2));
            float mn = fmaxf(m1r, tm);
            float corr = exp2f(m1r - mn);
            m1r = mn;
            float rs = 0.f;
            #pragma unroll
            for (int j = 0; j < 8; j++) {
                S[j][2] = exp2f(S[j][2] - mn);
                S[j][3] = exp2f(S[j][3] - mn);
                rs += S[j][2] + S[j][3];
            }
            rs += __shfl_xor_sync(0xffffffffu, rs, 1);
            rs += __shfl_xor_sync(0xffffffffu, rs, 2);
            l1r = l1r * corr + rs;
            #pragma unroll
            for (int j = 0; j < 8; j++) { O[j][2] *= corr; O[j][3] *= corr; }
        }

        // ---- O += P V ----
        #pragma unroll
        for (int kt = 0; kt < 4; kt++) {
            uint32_t ph[4];
            ph[0] = pack_h2(S[2*kt][0],   S[2*kt][1]);
            ph[1] = pack_h2(S[2*kt][2],   S[2*kt][3]);
            ph[2] = pack_h2(S[2*kt+1][0], S[2*kt+1][1]);
            ph[3] = pack_h2(S[2*kt+1][2], S[2*kt+1][3]);
            #pragma unroll
            for (int g = 0; g < 4; g++) {
                int vrow = kt*16 + (lane & 15);
                int vseg = g*2 + (lane >> 4);
                uint32_t voff = (uint32_t)vrow * 128u + (uint32_t)((vseg ^ lswz) << 4);
                uint32_t vf[4];
                LDSM_X4_T(vf, bb + AT3 + voff);
                MMAH(O[2*g],   ph, vf[0], vf[1]);
                MMAH(O[2*g+1], ph, vf[2], vf[3]);
            }
        }
    }

    // ---- epilogue: ctx single fp16 into out-proj input ----
    float inv0 = 1.f / l0r, inv1 = 1.f / l1r;
    int tg0 = t0 + r0l;
    #pragma unroll
    for (int j = 0; j < 8; j++) {
        int d = h * 64 + 8*j + cb;
        {
            size_t ad = ((size_t)tg0 * Bn + b) * En + d;
            *(uint32_t*)(g_x + ad) = pack_h2(O[j][0] * inv0, O[j][1] * inv0);
        }
        {
            size_t ad = ((size_t)(tg0 + 8) * Bn + b) * En + d;
            *(uint32_t*)(g_x + ad) = pack_h2(O[j][2] * inv1, O[j][3] * inv1);
        }
    }
}

// ---------------- launch ----------------
extern "C" void kernel_launch(void* const* d_in, const int* in_sizes, int n_in,
                              void* d_out, int out_size) {
    const float* query  = (const float*)d_in[0];
    const float* q_w    = (const float*)d_in[1];
    const float* q_b    = (const float*)d_in[2];
    const float* k_w    = (const float*)d_in[3];
    const float* k_b    = (const float*)d_in[4];
    const float* v_w    = (const float*)d_in[5];
    const float* v_b    = (const float*)d_in[6];
    const float* out_w  = (const float*)d_in[7];
    const float* out_b  = (const float*)d_in[8];
    const float* rel_bias = (const float*)d_in[9];
    const float* grep_w = (const float*)d_in[10];
    const float* grep_b = (const float*)d_in[11];
    const float* grep_a = (const float*)d_in[12];
    float* out = (float*)d_out;

    __half *p_x, *p_w;
    cudaGetSymbolAddress((void**)&p_x, g_x);
    cudaGetSymbolAddress((void**)&p_w, g_w);

    cudaFuncSetAttribute(gemm_qkv, cudaFuncAttributeMaxDynamicSharedMemorySize, SMEM_G);
    cudaFuncSetAttribute(gemm_out, cudaFuncAttributeMaxDynamicSharedMemorySize, SMEM_G);
    cudaFuncSetAttribute(attn_mma, cudaFuncAttributeMaxDynamicSharedMemorySize, ASM_TOTAL);

    prep_kernel<<<PREP_BLOCKS, 256>>>(query, q_w, k_w, v_w, out_w,
                                      rel_bias, grep_w, grep_b, grep_a);

    dim3 gq(24, (Tn*Bn)/128);      // (24, 32)
    gemm_qkv<<<gq, 256, SMEM_G>>>(p_x, q_b, k_b, v_b);

    dim3 ga(Tn/128, Hn, Bn);       // (8, 16, 4)
    attn_mma<<<ga, 256, ASM_TOTAL>>>();

    const int NW = En*En;
    dim3 gg(En/128, (Tn*Bn)/128);  // (8, 32)
    gemm_out<<<gg, 256, SMEM_G>>>(p_x, p_w + 3*(size_t)NW, out_b, out);

    (void)in_sizes; (void)n_in; (void)out_size;
}

// round 17
// speedup vs baseline: 1.0554x; 1.0554x over previous
#include <cuda_runtime.h>
#include <cuda_fp16.h>
#include <math.h>
#include <cstdint>

#define Tn 1024
#define Bn 4
#define En 1024
#define Hn 16
#define DHn 64
#define RSPAN (2*Tn - 1)   // 2047
#define LOG2E 1.4426950408889634f

// ---------------- scratch ----------------
__device__ float g_gate[Bn*Hn*Tn];
__device__ float g_posb[Hn*RSPAN];

__device__ __half g_x[(size_t)Tn*Bn*En];       // activations (query, later ctx)
__device__ __half g_w[4][(size_t)En*En];       // weights

__device__ __half g_q1[(size_t)Bn*Hn*Tn*DHn];  // [B,H,T,DH]
__device__ __half g_k1[(size_t)Bn*Hn*Tn*DHn];
__device__ __half g_v1[(size_t)Bn*Hn*Tn*DHn];

// ================= helpers =================
__device__ __forceinline__ uint32_t smem_u32(const void* p) {
    uint32_t a;
    asm("{ .reg .u64 t; cvta.to.shared.u64 t, %1; cvt.u32.u64 %0, t; }" : "=r"(a) : "l"(p));
    return a;
}
__device__ __forceinline__ void cpa16(uint32_t dst, const void* src) {
    asm volatile("cp.async.cg.shared.global [%0], [%1], 16;" :: "r"(dst), "l"(src));
}
#define CP_COMMIT() asm volatile("cp.async.commit_group;" ::: "memory")
#define CP_WAIT(n)  asm volatile("cp.async.wait_group %0;" :: "n"(n) : "memory")

#define LDSM_X4(r, a) \
    asm volatile("ldmatrix.sync.aligned.m8n8.x4.shared.b16 {%0,%1,%2,%3}, [%4];" \
        : "=r"((r)[0]), "=r"((r)[1]), "=r"((r)[2]), "=r"((r)[3]) : "r"(a))
#define LDSM_X4_T(r, a) \
    asm volatile("ldmatrix.sync.aligned.m8n8.x4.trans.shared.b16 {%0,%1,%2,%3}, [%4];" \
        : "=r"((r)[0]), "=r"((r)[1]), "=r"((r)[2]), "=r"((r)[3]) : "r"(a))

#define MMAH(c, a, b0, b1) \
    asm volatile("mma.sync.aligned.m16n8k16.row.col.f32.f16.f16.f32 " \
        "{%0,%1,%2,%3}, {%4,%5,%6,%7}, {%8,%9}, {%0,%1,%2,%3};" \
        : "+f"((c)[0]), "+f"((c)[1]), "+f"((c)[2]), "+f"((c)[3]) \
        : "r"((a)[0]), "r"((a)[1]), "r"((a)[2]), "r"((a)[3]), "r"(b0), "r"(b1))

__device__ __forceinline__ uint32_t pack_h2(float lo, float hi) {
    uint32_t r;
    asm("cvt.rn.f16x2.f32 %0, %1, %2;" : "=r"(r) : "f"(hi), "f"(lo));
    return r;
}

// ================= fp16 GEMM (BK=64, 3-stage, 2 CTAs/SM) =================
#define TILE_B 16384             // 128 rows x 128 B
#define STAGE_B (2*TILE_B)       // A + W = 32768
#define NSTG 3
#define SMEM_G (NSTG*STAGE_B)    // 98304
#define NCH 16                   // K chunks of 64

__device__ __forceinline__ void load_tile_mma(uint32_t sdst, const __half* g,
                                              int r0, int kc, int tid) {
    #pragma unroll
    for (int it = 0; it < 4; it++) {
        int idx = tid + it * 256;
        int row = idx >> 3, seg = idx & 7;
        uint32_t dst = sdst + (uint32_t)row * 128u + (uint32_t)((seg ^ (row & 7)) << 4);
        const char* src = (const char*)(g + (size_t)(r0 + row) * 1024 + kc * 64 + seg * 8);
        cpa16(dst, src);
    }
}
__device__ __forceinline__ void load_stage(uint32_t bb,
        const __half* A, const __half* W, int m0, int n0, int kc, int tid) {
    load_tile_mma(bb, A, m0, kc, tid);
    load_tile_mma(bb + TILE_B, W, n0, kc, tid);
    CP_COMMIT();
}

__device__ __forceinline__ void gemm_mainloop(uint32_t sb,
        const __half* A, const __half* W,
        int m0, int n0, int tid, int wid, int lane, float acc[4][4][4]) {
    int warp_m = wid & 1;
    int warp_n = wid >> 1;
    const int lswz = lane & 7;
    const int ahib = lane >> 4;
    const int bhib = (lane >> 3) & 1;
    uint32_t a_base[4];
    #pragma unroll
    for (int mi = 0; mi < 4; mi++) {
        int arow = warp_m * 64 + mi * 16 + (lane & 15);
        a_base[mi] = (uint32_t)arow * 128u;
    }
    uint32_t b_base[2];
    #pragma unroll
    for (int nip = 0; nip < 2; nip++) {
        int nrow = warp_n * 32 + nip * 16 + ((lane >> 4) & 1) * 8 + (lane & 7);
        b_base[nip] = (uint32_t)nrow * 128u;
    }

    load_stage(sb + 0 * STAGE_B, A, W, m0, n0, 0, tid);
    load_stage(sb + 1 * STAGE_B, A, W, m0, n0, 1, tid);

    #pragma unroll 1
    for (int kc = 0; kc < NCH; kc++) {
        if (kc < NCH - 1) CP_WAIT(1); else CP_WAIT(0);
        __syncthreads();
        if (kc + 2 < NCH)
            load_stage(sb + ((kc + 2) % NSTG) * STAGE_B, A, W, m0, n0, kc + 2, tid);
        uint32_t bb = sb + (kc % NSTG) * STAGE_B;
        uint32_t At = bb, Wt = bb + TILE_B;
        #pragma unroll
        for (int ks = 0; ks < 4; ks++) {
            uint32_t asg = (uint32_t)(((ks * 2 + ahib) ^ lswz) << 4);
            uint32_t bsg = (uint32_t)(((ks * 2 + bhib) ^ lswz) << 4);
            uint32_t af[4][4], bf[2][4];
            #pragma unroll
            for (int nip = 0; nip < 2; nip++)
                LDSM_X4(bf[nip], Wt + b_base[nip] + bsg);
            #pragma unroll
            for (int mi = 0; mi < 4; mi++)
                LDSM_X4(af[mi], At + a_base[mi] + asg);
            #pragma unroll
            for (int mi = 0; mi < 4; mi++) {
                #pragma unroll
                for (int ni = 0; ni < 4; ni++) {
                    int nip = ni >> 1, hf = (ni & 1) * 2;
                    MMAH(acc[mi][ni], af[mi], bf[nip][hf], bf[nip][hf + 1]);
                }
            }
        }
    }
}

// fused QKV: grid (24, 32)
__global__ void __launch_bounds__(256, 2)
gemm_qkv(const __half* __restrict__ A,
         const float* __restrict__ q_b, const float* __restrict__ k_b,
         const float* __restrict__ v_b) {
    extern __shared__ char smraw[];
    uint32_t sb = smem_u32(smraw);
    int tid = threadIdx.x, wid = tid >> 5, lane = tid & 31;
    int w = blockIdx.x >> 3;
    int n0 = (blockIdx.x & 7) * 128, m0 = blockIdx.y * 128;

    const size_t NW = (size_t)En * En;
    const __half* W = &g_w[0][0] + (size_t)w * NW;
    const float* bias = (w == 0) ? q_b : (w == 1) ? k_b : v_b;
    __half* dst = (w == 0) ? g_q1 : (w == 1) ? g_k1 : g_v1;
    float scale = (w == 0) ? 0.125f * LOG2E : 1.0f;

    float acc[4][4][4];
    #pragma unroll
    for (int i = 0; i < 4; i++)
        #pragma unroll
        for (int j = 0; j < 4; j++)
            #pragma unroll
            for (int q = 0; q < 4; q++) acc[i][j][q] = 0.f;

    gemm_mainloop(sb, A, W, m0, n0, tid, wid, lane, acc);

    int rbase = m0 + (wid & 1) * 64 + (lane >> 2);
    int cbase = n0 + (wid >> 1) * 32 + (lane & 3) * 2;
    #pragma unroll
    for (int mi = 0; mi < 4; mi++) {
        #pragma unroll
        for (int ni = 0; ni < 4; ni++) {
            int c = cbase + ni * 8;
            float b0 = bias[c], b1 = bias[c + 1];
            #pragma unroll
            for (int half = 0; half < 2; half++) {
                int r = rbase + mi * 16 + half * 8;
                float v0 = (acc[mi][ni][half * 2 + 0] + b0) * scale;
                float v1 = (acc[mi][ni][half * 2 + 1] + b1) * scale;
                int t = r >> 2, b = r & 3;
                int h = c >> 6, d = c & 63;
                size_t ad = ((size_t)(b * Hn + h) * Tn + t) * DHn + d;
                *(uint32_t*)(dst + ad) = pack_h2(v0, v1);
            }
        }
    }
}

// out projection: fp32 output
__global__ void __launch_bounds__(256, 2)
gemm_out(const __half* __restrict__ A, const __half* __restrict__ W,
         const float* __restrict__ bias, float* __restrict__ outf) {
    extern __shared__ char smraw[];
    uint32_t sb = smem_u32(smraw);
    int tid = threadIdx.x, wid = tid >> 5, lane = tid & 31;
    int n0 = blockIdx.x * 128, m0 = blockIdx.y * 128;

    float acc[4][4][4];
    #pragma unroll
    for (int i = 0; i < 4; i++)
        #pragma unroll
        for (int j = 0; j < 4; j++)
            #pragma unroll
            for (int q = 0; q < 4; q++) acc[i][j][q] = 0.f;

    gemm_mainloop(sb, A, W, m0, n0, tid, wid, lane, acc);

    int rbase = m0 + (wid & 1) * 64 + (lane >> 2);
    int cbase = n0 + (wid >> 1) * 32 + (lane & 3) * 2;
    #pragma unroll
    for (int mi = 0; mi < 4; mi++) {
        #pragma unroll
        for (int ni = 0; ni < 4; ni++) {
            int c = cbase + ni * 8;
            float b0 = bias[c], b1 = bias[c + 1];
            #pragma unroll
            for (int half = 0; half < 2; half++) {
                int r = rbase + mi * 16 + half * 8;
                float2 v;
                v.x = acc[mi][ni][half * 2 + 0] + b0;
                v.y = acc[mi][ni][half * 2 + 1] + b1;
                *(float2*)(outf + (size_t)r * 1024 + c) = v;
            }
        }
    }
}

// ================= fused prep (8 floats/thread) =================
// [0,2048): query; [2048,4096): weights; [4096,4104): posb; [4104,12296): gate
#define PREP_BLOCKS 12296

__global__ void prep_kernel(const float* __restrict__ query,
                            const float* __restrict__ q_w, const float* __restrict__ k_w,
                            const float* __restrict__ v_w, const float* __restrict__ out_w,
                            const float* __restrict__ rel_bias,
                            const float* __restrict__ grep_w,
                            const float* __restrict__ grep_b,
                            const float* __restrict__ grep_a) {
    int bx = blockIdx.x, tid = threadIdx.x;
    if (bx < 2048) {
        size_t i = ((size_t)bx * 256 + tid) * 8;
        float4 v0 = *(const float4*)(query + i);
        float4 v1 = *(const float4*)(query + i + 4);
        uint32_t* xp = (uint32_t*)(g_x + i);
        xp[0] = pack_h2(v0.x, v0.y);
        xp[1] = pack_h2(v0.z, v0.w);
        xp[2] = pack_h2(v1.x, v1.y);
        xp[3] = pack_h2(v1.z, v1.w);
    } else if (bx < 4096) {
        const int NW = En * En;
        size_t i = ((size_t)(bx - 2048) * 256 + tid) * 8;
        int w = (int)(i / NW);
        size_t off = i - (size_t)w * NW;
        const float* src = (w == 0) ? q_w : (w == 1) ? k_w : (w == 2) ? v_w : out_w;
        float4 v0 = *(const float4*)(src + off);
        float4 v1 = *(const float4*)(src + off + 4);
        uint32_t* wp = (uint32_t*)(&g_w[0][0] + i);
        wp[0] = pack_h2(v0.x, v0.y);
        wp[1] = pack_h2(v0.z, v0.w);
        wp[2] = pack_h2(v1.x, v1.y);
        wp[3] = pack_h2(v1.z, v1.w);
    } else if (bx < 4104) {
        int idx = (bx - 4096) * 256 + tid;
        if (idx >= RSPAN) return;
        int rp = idx - (Tn - 1);
        const int n = 16, max_exact = 8;
        int bucket = (rp > 0) ? n : 0;
        int arp = abs(rp);
        int add;
        if (arp < max_exact) add = arp;
        else {
            float v = (log2f((float)arp) - 3.0f) * 2.0f;
            add = max_exact + (int)v;
            if (add > n - 1) add = n - 1;
        }
        bucket += add;
        #pragma unroll
        for (int h = 0; h < Hn; h++)
            g_posb[h*RSPAN + idx] = rel_bias[bucket*Hn + h];
    } else {
        int warp = (bx - 4104) * 8 + (tid >> 5);   // 8192 blocks -> 65536 warps
        int lane = tid & 31;
        int t = warp % Tn;
        int h = (warp / Tn) % Hn;
        int b = warp / (Tn * Hn);
        const float* q = query + ((size_t)t*Bn + b)*En + h*DHn;
        float q0 = q[lane], q1 = q[lane + 32];
        float s0 = 0.f, s1 = 0.f;
        #pragma unroll
        for (int e = 0; e < 8; e++) {
            float p = q0 * grep_w[e*DHn + lane] + q1 * grep_w[e*DHn + lane + 32];
            #pragma unroll
            for (int o = 16; o; o >>= 1) p += __shfl_xor_sync(0xffffffffu, p, o);
            p += grep_b[e];
            if (e < 4) s0 += p; else s1 += p;
        }
        if (lane == 0) {
            float ga = 1.f / (1.f + __expf(-s0));
            float gb = 1.f / (1.f + __expf(-s1));
            g_gate[warp] = (ga * (gb * grep_a[h] - 1.0f) + 2.0f) * LOG2E;
        }
    }
}

// ================= fp16 flash attention (128 q-rows, 8 warps, 5-stage, 2 CTAs/SM) =================
#define AT3   8192                  // 64 rows x 128 B per KV tile
#define ASTG2 (2*AT3)               // K + V = 16384 per stage
#define ANST  5
#define ASM_Q  (ANST*ASTG2)         // 81920 : Q (128 rows x 128 B = 16384)
#define ASM_LS (ASM_Q + 16384)      // 98304 : Ls[5][192] floats
#define ASM_GS (ASM_LS + ANST*192*4)// 102144 : gs 128 floats
#define ASM_TOTAL (ASM_GS + 768)    // 102912
#define NTILE 16

__device__ __forceinline__ void attn_load_kv(uint32_t bbase,
        const __half* kk, const __half* vv, int s0, int tid) {
    #pragma unroll
    for (int it = 0; it < 2; it++) {
        int idx = tid + it * 256;
        int row = idx >> 3, seg = idx & 7;
        uint32_t doff = (uint32_t)row * 128u + (uint32_t)((seg ^ (row & 7)) << 4);
        size_t goff = (size_t)(s0 + row) * 64 + seg * 8;
        cpa16(bbase + doff, kk + goff);
        cpa16(bbase + AT3 + doff, vv + goff);
    }
    CP_COMMIT();
}

__global__ void __launch_bounds__(256, 2) attn_mma() {
    extern __shared__ char smraw[];
    uint32_t sb = smem_u32(smraw);
    float* Lsf = (float*)(smraw + ASM_LS);
    float* gsf = (float*)(smraw + ASM_GS);
    const int tid = threadIdx.x, wid = tid >> 5, lane = tid & 31;
    const int t0 = blockIdx.x * 128;
    const int h = blockIdx.y, b = blockIdx.z;
    const size_t hoff = (size_t)(b*Hn + h) * Tn * DHn;
    const __half *qg = g_q1 + hoff;
    const __half *kkg = g_k1 + hoff, *vvg = g_v1 + hoff;
    const int lswz = lane & 7;

    // ---- prologue: Q group first, then KV stages 0..3 ----
    #pragma unroll
    for (int it = 0; it < 4; it++) {
        int idx = tid + it * 256;
        int row = idx >> 3, seg = idx & 7;
        uint32_t doff = (uint32_t)row * 128u + (uint32_t)((seg ^ (row & 7)) << 4);
        size_t goff = (size_t)(t0 + row) * 64 + seg * 8;
        cpa16(sb + ASM_Q + doff, qg + goff);
    }
    CP_COMMIT();
    #pragma unroll
    for (int ps = 0; ps < 4; ps++)
        attn_load_kv(sb + ps * ASTG2, kkg, vvg, ps * 64, tid);
    if (tid < 128) gsf[tid] = g_gate[(b*Hn + h)*Tn + t0 + tid];
    if (tid < 191) {
        #pragma unroll
        for (int ps = 0; ps < 4; ps++)
            Lsf[ps*192 + tid] = g_posb[h*RSPAN + 1023 + (ps*64 - t0) + tid - 127];
    }
    CP_WAIT(4); __syncthreads();    // Q complete (4 younger KV groups pending)

    uint32_t qf[4][4];
    {
        int arow = wid * 16 + (lane & 15);
        #pragma unroll
        for (int kt = 0; kt < 4; kt++) {
            int seg = kt * 2 + (lane >> 4);
            uint32_t aoff = (uint32_t)arow * 128u + (uint32_t)((seg ^ (arow & 7)) << 4);
            LDSM_X4(qf[kt], sb + ASM_Q + aoff);
        }
    }

    float O[8][4];
    #pragma unroll
    for (int j = 0; j < 8; j++) { O[j][0]=0.f; O[j][1]=0.f; O[j][2]=0.f; O[j][3]=0.f; }
    float m0r = -1e30f, m1r = -1e30f, l0r = 0.f, l1r = 0.f;

    const int r0l = wid * 16 + (lane >> 2);   // 0..127
    const int cb  = (lane & 3) * 2;
    const float g0 = gsf[r0l], g1 = gsf[r0l + 8];
    const int ib0 = 127 - r0l + cb;
    const int ib1 = ib0 - 8;

    #pragma unroll 1
    for (int st = 0; st < NTILE; st++) {
        CP_WAIT(3);
        __syncthreads();
        if (st + 4 < NTILE) {
            int ns = (st + 4) % ANST;
            attn_load_kv(sb + ns * ASTG2, kkg, vvg, (st + 4) * 64, tid);
            if (tid < 191)
                Lsf[ns * 192 + tid] =
                    g_posb[h*RSPAN + 1023 + ((st + 4) * 64 - t0) + tid - 127];
        } else {
            CP_COMMIT();
        }
        uint32_t bb = sb + (st % ANST) * ASTG2;
        float* Lss = Lsf + (st % ANST) * 192;

        // ---- S init = gate*posb; S += Q K^T ----
        float S[8][4];
        #pragma unroll
        for (int j = 0; j < 8; j++) {
            S[j][0] = g0 * Lss[ib0 + 8*j];
            S[j][1] = g0 * Lss[ib0 + 8*j + 1];
            S[j][2] = g1 * Lss[ib1 + 8*j];
            S[j][3] = g1 * Lss[ib1 + 8*j + 1];
        }
        #pragma unroll
        for (int kt = 0; kt < 4; kt++) {
            #pragma unroll
            for (int nip = 0; nip < 4; nip++) {
                int krow = nip*16 + ((lane >> 4) & 1)*8 + (lane & 7);
                int kseg = kt*2 + ((lane >> 3) & 1);
                uint32_t boff = (uint32_t)krow * 128u + (uint32_t)((kseg ^ lswz) << 4);
                uint32_t bf[4];
                LDSM_X4(bf, bb + boff);
                MMAH(S[nip*2 + 0], qf[kt], bf[0], bf[1]);
                MMAH(S[nip*2 + 1], qf[kt], bf[2], bf[3]);
            }
        }

        // ---- online softmax (base-2) ----
        {
            float tm = fmaxf(S[0][0], S[0][1]);
            #pragma unroll
            for (int j = 1; j < 8; j++) tm = fmaxf(tm, fmaxf(S[j][0], S[j][1]));
            tm = fmaxf(tm, __shfl_xor_sync(0xffffffffu, tm, 1));
            tm = fmaxf(tm, __shfl_xor_sync(0xffffffffu, tm, 2));
            float mn = fmaxf(m0r, tm);
            float corr = exp2f(m0r - mn);
            m0r = mn;
            float rs = 0.f;
            #pragma unroll
            for (int j = 0; j < 8; j++) {
                S[j][0] = exp2f(S[j][0] - mn);
                S[j][1] = exp2f(S[j][1] - mn);
                rs += S[j][0] + S[j][1];
            }
            rs += __shfl_xor_sync(0xffffffffu, rs, 1);
            rs += __shfl_xor_sync(0xffffffffu, rs, 2);
            l0r = l0r * corr + rs;
            #pragma unroll
            for (int j = 0; j < 8; j++) { O[j][0] *= corr; O[j][1] *= corr; }
        }
        {
            float tm = fmaxf(S[0][2], S[0][3]);
            #pragma unroll
            for (int j = 1; j < 8; j++) tm = fmaxf(tm, fmaxf(S[j][2], S[j][3]));
            tm = fmaxf(tm, __shfl_xor_sync(0xffffffffu, tm, 1));
            tm = fmaxf(tm, __shfl_xor_sync(0xffffffffu, tm, 2));
            float mn = fmaxf(m1r, tm);
            float corr = exp2f(m1r - mn);
            m1r = mn;
            float rs = 0.f;
            #pragma unroll
            for (int j = 0; j < 8; j++) {
                S[j][2] = exp2f(S[j][2] - mn);
                S[j][3] = exp2f(S[j][3] - mn);
                rs += S[j][2] + S[j][3];
            }
            rs += __shfl_xor_sync(0xffffffffu, rs, 1);
            rs += __shfl_xor_sync(0xffffffffu, rs, 2);
            l1r = l1r * corr + rs;
            #pragma unroll
            for (int j = 0; j < 8; j++) { O[j][2] *= corr; O[j][3] *= corr; }
        }

        // ---- O += P V ----
        #pragma unroll
        for (int kt = 0; kt < 4; kt++) {
            uint32_t ph[4];
            ph[0] = pack_h2(S[2*kt][0],   S[2*kt][1]);
            ph[1] = pack_h2(S[2*kt][2],   S[2*kt][3]);
            ph[2] = pack_h2(S[2*kt+1][0], S[2*kt+1][1]);
            ph[3] = pack_h2(S[2*kt+1][2], S[2*kt+1][3]);
            #pragma unroll
            for (int g = 0; g < 4; g++) {
                int vrow = kt*16 + (lane & 15);
                int vseg = g*2 + (lane >> 4);
                uint32_t voff = (uint32_t)vrow * 128u + (uint32_t)((vseg ^ lswz) << 4);
                uint32_t vf[4];
                LDSM_X4_T(vf, bb + AT3 + voff);
                MMAH(O[2*g],   ph, vf[0], vf[1]);
                MMAH(O[2*g+1], ph, vf[2], vf[3]);
            }
        }
    }

    // ---- epilogue: ctx single fp16 into out-proj input ----
    float inv0 = 1.f / l0r, inv1 = 1.f / l1r;
    int tg0 = t0 + r0l;
    #pragma unroll
    for (int j = 0; j < 8; j++) {
        int d = h * 64 + 8*j + cb;
        {
            size_t ad = ((size_t)tg0 * Bn + b) * En + d;
            *(uint32_t*)(g_x + ad) = pack_h2(O[j][0] * inv0, O[j][1] * inv0);
        }
        {
            size_t ad = ((size_t)(tg0 + 8) * Bn + b) * En + d;
            *(uint32_t*)(g_x + ad) = pack_h2(O[j][2] * inv1, O[j][3] * inv1);
        }
    }
}

// ---------------- launch ----------------
extern "C" void kernel_launch(void* const* d_in, const int* in_sizes, int n_in,
                              void* d_out, int out_size) {
    const float* query  = (const float*)d_in[0];
    const float* q_w    = (const float*)d_in[1];
    const float* q_b    = (const float*)d_in[2];
    const float* k_w    = (const float*)d_in[3];
    const float* k_b    = (const float*)d_in[4];
    const float* v_w    = (const float*)d_in[5];
    const float* v_b    = (const float*)d_in[6];
    const float* out_w  = (const float*)d_in[7];
    const float* out_b  = (const float*)d_in[8];
    const float* rel_bias = (const float*)d_in[9];
    const float* grep_w = (const float*)d_in[10];
    const float* grep_b = (const float*)d_in[11];
    const float* grep_a = (const float*)d_in[12];
    float* out = (float*)d_out;

    __half *p_x, *p_w;
    cudaGetSymbolAddress((void**)&p_x, g_x);
    cudaGetSymbolAddress((void**)&p_w, g_w);

    cudaFuncSetAttribute(gemm_qkv, cudaFuncAttributeMaxDynamicSharedMemorySize, SMEM_G);
    cudaFuncSetAttribute(gemm_out, cudaFuncAttributeMaxDynamicSharedMemorySize, SMEM_G);
    cudaFuncSetAttribute(attn_mma, cudaFuncAttributeMaxDynamicSharedMemorySize, ASM_TOTAL);

    prep_kernel<<<PREP_BLOCKS, 256>>>(query, q_w, k_w, v_w, out_w,
                                      rel_bias, grep_w, grep_b, grep_a);

    dim3 gq(24, (Tn*Bn)/128);      // (24, 32)
    gemm_qkv<<<gq, 256, SMEM_G>>>(p_x, q_b, k_b, v_b);

    dim3 ga(Tn/128, Hn, Bn);       // (8, 16, 4)
    attn_mma<<<ga, 256, ASM_TOTAL>>>();

    const int NW = En*En;
    dim3 gg(En/128, (Tn*Bn)/128);  // (8, 32)
    gemm_out<<<gg, 256, SMEM_G>>>(p_x, p_w + 3*(size_t)NW, out_b, out);

    (void)in_sizes; (void)n_in; (void)out_size;
}